// round 5
// baseline (speedup 1.0000x reference)
#include <cuda_runtime.h>
#include <cuda_bf16.h>

#define BB 32
#define TT 4096
#define HH 256
#define CHUNKS 64                        // blocks per batch row
#define ROWS_PER_BLOCK (TT / CHUNKS)     // 64
#define NTHREADS 128
#define NWARPS (NTHREADS / 32)           // 4
#define ROWS_PER_WARP (ROWS_PER_BLOCK / NWARPS) // 16
#define GRID (BB * CHUNKS)               // 2048

#define ALPHA 0.1f
#define LOG2_09 (-0.15200309344504997f)  // log2(0.9)
#define INV_09  (1.1111111111111112f)    // 1/0.9
#define MASK_PENALTY 1000000.0f

__device__ float g_partial[GRID];
__device__ unsigned int g_count = 0;

__global__ __launch_bounds__(NTHREADS, 8)
void pool_fused(const float* __restrict__ x,
                const int*   __restrict__ mask,
                const float* __restrict__ weight_ema,
                const float* __restrict__ weight_mean,
                const float* __restrict__ W,
                const float* __restrict__ bias,
                float*       __restrict__ out)
{
    const int b     = blockIdx.x / CHUNKS;
    const int chunk = blockIdx.x % CHUNKS;
    const int tid   = threadIdx.x;
    const int wid   = tid >> 5;
    const int lane  = tid & 31;

    __shared__ float s_warp_acc[NWARPS];
    __shared__ bool  s_is_last;

    // Per-lane W slices (each lane owns 8 of the 256 W values)
    const float4* W4 = reinterpret_cast<const float4*>(W);
    const float4 wa = __ldg(W4 + lane);        // W[lane*4 .. +3]
    const float4 wb = __ldg(W4 + 32 + lane);   // W[128 + lane*4 .. +3]

    // Warp-wide Wsum (identical in every warp -> deterministic)
    float wsum = wa.x + wa.y + wa.z + wa.w + wb.x + wb.y + wb.z + wb.w;
    #pragma unroll
    for (int off = 16; off > 0; off >>= 1)
        wsum += __shfl_xor_sync(0xffffffffu, wsum, off);

    const float we        = __ldg(weight_ema);
    const float wm_over_T = __ldg(weight_mean) * (1.0f / (float)TT);
    const float cs        = we * ALPHA;        // coefficient on 0.9^(T-1-t), t>0

    const int t_base = chunk * ROWS_PER_BLOCK + wid * ROWS_PER_WARP;
    const float4* xbase = reinterpret_cast<const float4*>(x) +
                          (size_t)(b * TT + t_base) * (HH / 4);
    const int* mrow = mask + b * TT + t_base;

    // Hoist mask: one load per warp, then a 16-bit mask of "penalized" rows.
    int mv = (lane < ROWS_PER_WARP) ? __ldg(mrow + lane) : 1;
    const unsigned penbits =
        __ballot_sync(0xffffffffu, (lane < ROWS_PER_WARP) && (mv == 0));

    // EMA weight recurrence: wt(i) = 0.9^(T-1 - (t_base+i)); wt *= 1/0.9 per row.
    float wt = exp2f((float)(TT - 1 - t_base) * LOG2_09);

    float acc     = 0.0f;  // per-lane weighted partial-dot accumulator
    float pen_sum = 0.0f;  // scalar penalty-weight sum (identical across lanes)

    // Double-buffered prefetch (depth 2)
    float4 A0 = __ldcs(xbase + lane);
    float4 C0 = __ldcs(xbase + 32 + lane);
    float4 A1 = __ldcs(xbase + (HH / 4) + lane);
    float4 C1 = __ldcs(xbase + (HH / 4) + 32 + lane);

    #pragma unroll
    for (int i = 0; i < ROWS_PER_WARP; i++) {
        float4 a  = A0;
        float4 c2 = C0;
        A0 = A1; C0 = C1;
        if (i + 2 < ROWS_PER_WARP) {
            const float4* p = xbase + (size_t)(i + 2) * (HH / 4);
            A1 = __ldcs(p + lane);
            C1 = __ldcs(p + 32 + lane);
        }

        // c = we * w_ema[t] + wm/T   (t=0 row has no alpha factor)
        float c;
        if (i == 0 && t_base == 0) c = fmaf(we, wt, wm_over_T);
        else                       c = fmaf(cs, wt, wm_over_T);
        wt *= INV_09;

        float pd = a.x * wa.x;
        pd = fmaf(a.y,  wa.y, pd);
        pd = fmaf(a.z,  wa.z, pd);
        pd = fmaf(a.w,  wa.w, pd);
        pd = fmaf(c2.x, wb.x, pd);
        pd = fmaf(c2.y, wb.y, pd);
        pd = fmaf(c2.z, wb.z, pd);
        pd = fmaf(c2.w, wb.w, pd);

        acc = fmaf(c, pd, acc);
        if ((penbits >> i) & 1u) pen_sum += c;
    }

    // Single butterfly per warp (fixed order -> deterministic)
    #pragma unroll
    for (int off = 16; off > 0; off >>= 1)
        acc += __shfl_xor_sync(0xffffffffu, acc, off);

    const float warp_total = acc - pen_sum * (MASK_PENALTY * wsum);
    if (lane == 0) s_warp_acc[wid] = warp_total;
    __syncthreads();

    if (tid == 0) {
        float v = 0.0f;
        #pragma unroll
        for (int w = 0; w < NWARPS; w++) v += s_warp_acc[w];  // fixed order
        g_partial[blockIdx.x] = v;
        __threadfence();
        unsigned ticket = atomicAdd(&g_count, 1u);
        s_is_last = (ticket == (unsigned)(GRID - 1));
    }
    __syncthreads();

    // Last block folds partials: 4 warps x 8 batches; lane covers 2 of the
    // 64 chunks. Fixed order -> deterministic.
    if (s_is_last) {
        const float bv = __ldg(bias);
        #pragma unroll
        for (int k = 0; k < BB / NWARPS; k++) {
            const int bb = wid * (BB / NWARPS) + k;
            float v = __ldcg(&g_partial[bb * CHUNKS + lane])
                    + __ldcg(&g_partial[bb * CHUNKS + 32 + lane]);
            #pragma unroll
            for (int off = 16; off > 0; off >>= 1)
                v += __shfl_xor_sync(0xffffffffu, v, off);
            if (lane == 0) out[bb] = v + bv;
        }
        if (tid == 0) g_count = 0;   // self-reset for next graph replay
    }
}

extern "C" void kernel_launch(void* const* d_in, const int* in_sizes, int n_in,
                              void* d_out, int out_size)
{
    const float* x    = (const float*)d_in[0];
    const int*   mask = (const int*)d_in[1];
    const float* we   = (const float*)d_in[2];
    const float* wm   = (const float*)d_in[3];
    const float* W    = (const float*)d_in[4];
    const float* bias = (const float*)d_in[5];
    float* out = (float*)d_out;

    pool_fused<<<GRID, NTHREADS>>>(x, mask, we, wm, W, bias, out);
}

// round 6
// speedup vs baseline: 1.0088x; 1.0088x over previous
#include <cuda_runtime.h>
#include <cuda_bf16.h>

#define BB 32
#define TT 4096
#define HH 256
#define CHUNKS 32                        // blocks per batch row
#define ROWS_PER_BLOCK (TT / CHUNKS)     // 128
#define NTHREADS 256
#define NWARPS (NTHREADS / 32)           // 8
#define ROWS_PER_WARP (ROWS_PER_BLOCK / NWARPS) // 16
#define GRID (BB * CHUNKS)               // 1024
#define PF 4                             // prefetch depth (rows in flight)

#define ALPHA 0.1f
#define LOG2_09 (-0.15200309344504997f)  // log2(0.9)
#define INV_09  (1.1111111111111112f)    // 1/0.9
#define MASK_PENALTY 1000000.0f

__device__ float g_partial[GRID];
__device__ unsigned int g_count = 0;

__global__ __launch_bounds__(NTHREADS, 3)   // <=85 regs: room for 4-deep buffers, no spill
void pool_fused(const float* __restrict__ x,
                const int*   __restrict__ mask,
                const float* __restrict__ weight_ema,
                const float* __restrict__ weight_mean,
                const float* __restrict__ W,
                const float* __restrict__ bias,
                float*       __restrict__ out)
{
    const int b     = blockIdx.x / CHUNKS;
    const int chunk = blockIdx.x % CHUNKS;
    const int tid   = threadIdx.x;
    const int wid   = tid >> 5;
    const int lane  = tid & 31;

    __shared__ float s_warp_acc[NWARPS];
    __shared__ bool  s_is_last;

    // Per-lane W slices (each lane owns 8 of the 256 W values)
    const float4* W4 = reinterpret_cast<const float4*>(W);
    const float4 wa = __ldg(W4 + lane);        // W[lane*4 .. +3]
    const float4 wb = __ldg(W4 + 32 + lane);   // W[128 + lane*4 .. +3]

    // Warp-wide Wsum (identical in every warp -> deterministic)
    float wsum = wa.x + wa.y + wa.z + wa.w + wb.x + wb.y + wb.z + wb.w;
    #pragma unroll
    for (int off = 16; off > 0; off >>= 1)
        wsum += __shfl_xor_sync(0xffffffffu, wsum, off);

    const float we        = __ldg(weight_ema);
    const float wm_over_T = __ldg(weight_mean) * (1.0f / (float)TT);
    const float cs        = we * ALPHA;        // coefficient on 0.9^(T-1-t), t>0

    const int t_base = chunk * ROWS_PER_BLOCK + wid * ROWS_PER_WARP;
    const float4* xbase = reinterpret_cast<const float4*>(x) +
                          (size_t)(b * TT + t_base) * (HH / 4);
    const int* mrow = mask + b * TT + t_base;

    // Hoist mask: one load per warp -> 16-bit mask of "penalized" rows.
    int mv = (lane < ROWS_PER_WARP) ? __ldg(mrow + lane) : 1;
    const unsigned penbits =
        __ballot_sync(0xffffffffu, (lane < ROWS_PER_WARP) && (mv == 0));

    // EMA weight recurrence: wt(i) = 0.9^(T-1 - (t_base+i)); wt *= 1/0.9 per row.
    float wt = exp2f((float)(TT - 1 - t_base) * LOG2_09);

    float acc     = 0.0f;  // per-lane weighted partial-dot accumulator
    float pen_sum = 0.0f;  // scalar penalty-weight sum (identical across lanes)

    // Rotating 4-deep prefetch: 4 rows (4 KB/warp) in flight at all times.
    float4 Abuf[PF], Cbuf[PF];
    #pragma unroll
    for (int k = 0; k < PF; k++) {
        const float4* p = xbase + (size_t)k * (HH / 4);
        Abuf[k] = __ldcs(p + lane);
        Cbuf[k] = __ldcs(p + 32 + lane);
    }

    #pragma unroll
    for (int i = 0; i < ROWS_PER_WARP; i++) {
        const int s = i & (PF - 1);
        float4 a  = Abuf[s];
        float4 c2 = Cbuf[s];
        if (i + PF < ROWS_PER_WARP) {
            const float4* p = xbase + (size_t)(i + PF) * (HH / 4);
            Abuf[s] = __ldcs(p + lane);
            Cbuf[s] = __ldcs(p + 32 + lane);
        }

        // c = we * w_ema[t] + wm/T   (t=0 row has no alpha factor)
        float c;
        if (i == 0 && t_base == 0) c = fmaf(we, wt, wm_over_T);
        else                       c = fmaf(cs, wt, wm_over_T);
        wt *= INV_09;

        // two independent FMA chains to halve dependent latency
        float p0 = a.x * wa.x;
        float p1 = a.y * wa.y;
        p0 = fmaf(a.z,  wa.z, p0);
        p1 = fmaf(a.w,  wa.w, p1);
        p0 = fmaf(c2.x, wb.x, p0);
        p1 = fmaf(c2.y, wb.y, p1);
        p0 = fmaf(c2.z, wb.z, p0);
        p1 = fmaf(c2.w, wb.w, p1);

        acc = fmaf(c, p0 + p1, acc);
        if ((penbits >> i) & 1u) pen_sum += c;
    }

    // Single butterfly per warp (fixed order -> deterministic)
    #pragma unroll
    for (int off = 16; off > 0; off >>= 1)
        acc += __shfl_xor_sync(0xffffffffu, acc, off);

    const float warp_total = acc - pen_sum * (MASK_PENALTY * wsum);
    if (lane == 0) s_warp_acc[wid] = warp_total;
    __syncthreads();

    if (tid == 0) {
        float v = 0.0f;
        #pragma unroll
        for (int w = 0; w < NWARPS; w++) v += s_warp_acc[w];  // fixed order
        g_partial[blockIdx.x] = v;
        __threadfence();
        unsigned ticket = atomicAdd(&g_count, 1u);
        s_is_last = (ticket == (unsigned)(GRID - 1));
    }
    __syncthreads();

    // Last block folds partials: warp w handles batches 4w..4w+3,
    // lane = chunk index (CHUNKS == 32). Fixed order -> deterministic.
    if (s_is_last) {
        const float bv = __ldg(bias);
        #pragma unroll
        for (int k = 0; k < BB / NWARPS; k++) {
            const int bb = wid * (BB / NWARPS) + k;
            float v = __ldcg(&g_partial[bb * CHUNKS + lane]);
            #pragma unroll
            for (int off = 16; off > 0; off >>= 1)
                v += __shfl_xor_sync(0xffffffffu, v, off);
            if (lane == 0) out[bb] = v + bv;
        }
        if (tid == 0) g_count = 0;   // self-reset for next graph replay
    }
}

extern "C" void kernel_launch(void* const* d_in, const int* in_sizes, int n_in,
                              void* d_out, int out_size)
{
    const float* x    = (const float*)d_in[0];
    const int*   mask = (const int*)d_in[1];
    const float* we   = (const float*)d_in[2];
    const float* wm   = (const float*)d_in[3];
    const float* W    = (const float*)d_in[4];
    const float* bias = (const float*)d_in[5];
    float* out = (float*)d_out;

    pool_fused<<<GRID, NTHREADS>>>(x, mask, we, wm, W, bias, out);
}

// round 8
// speedup vs baseline: 1.0099x; 1.0011x over previous
#include <cuda_runtime.h>
#include <cuda_bf16.h>

#define BB 32
#define TT 4096
#define HH 256
#define TILE_ROWS 64
#define CHUNKS (TT / TILE_ROWS)          // 64 chunks per batch
#define NTILES (BB * CHUNKS)             // 2048 work tiles
#define NTHREADS 256
#define NWARPS (NTHREADS / 32)           // 8
#define ROWS_PER_WARP (TILE_ROWS / NWARPS) // 8
#define OCC 3
#define GRID (148 * OCC)                 // 444: exactly one wave at occ=3
#define PF 4                             // prefetch depth (rows in flight)

#define ALPHA 0.1f
#define LOG2_09 (-0.15200309344504997f)  // log2(0.9)
#define INV_09  (1.1111111111111112f)    // 1/0.9
#define MASK_PENALTY 1000000.0f

__device__ float g_partial[NTILES];
__device__ unsigned int g_work = 0;
__device__ unsigned int g_done = 0;

__global__ __launch_bounds__(NTHREADS, OCC)
void pool_persistent(const float* __restrict__ x,
                     const int*   __restrict__ mask,
                     const float* __restrict__ weight_ema,
                     const float* __restrict__ weight_mean,
                     const float* __restrict__ W,
                     const float* __restrict__ bias,
                     float*       __restrict__ out)
{
    const int tid  = threadIdx.x;
    const int wid  = tid >> 5;
    const int lane = tid & 31;

    __shared__ float s_warp_acc[NWARPS];
    __shared__ int   s_tile;
    __shared__ bool  s_is_last;

    // Per-lane W slices (each lane owns 8 of the 256 W values)
    const float4* W4 = reinterpret_cast<const float4*>(W);
    const float4 wa = __ldg(W4 + lane);        // W[lane*4 .. +3]
    const float4 wb = __ldg(W4 + 32 + lane);   // W[128 + lane*4 .. +3]

    // Warp-wide Wsum (identical in every warp -> deterministic)
    float wsum = wa.x + wa.y + wa.z + wa.w + wb.x + wb.y + wb.z + wb.w;
    #pragma unroll
    for (int off = 16; off > 0; off >>= 1)
        wsum += __shfl_xor_sync(0xffffffffu, wsum, off);

    const float we        = __ldg(weight_ema);
    const float wm_over_T = __ldg(weight_mean) * (1.0f / (float)TT);
    const float cs        = we * ALPHA;     // coeff on 0.9^(T-1-t), t>0
    const float penw      = MASK_PENALTY * wsum;

    // ---- dynamic work loop: one 64-row tile per ticket ----
    while (true) {
        if (tid == 0) s_tile = (int)atomicAdd(&g_work, 1u);
        __syncthreads();
        const int tile = s_tile;
        if (tile >= NTILES) break;

        const int b     = tile / CHUNKS;
        const int chunk = tile % CHUNKS;
        const int t0    = chunk * TILE_ROWS + wid * ROWS_PER_WARP;

        const float4* xbase = reinterpret_cast<const float4*>(x) +
                              (size_t)(b * TT + t0) * (HH / 4);
        const int* mrow = mask + b * TT + t0;

        // mask bits for this warp's 8 rows (one broadcast load + ballot)
        int mv = (lane < ROWS_PER_WARP) ? __ldg(mrow + lane) : 1;
        const unsigned penbits =
            __ballot_sync(0xffffffffu, (lane < ROWS_PER_WARP) && (mv == 0));

        // EMA weight recurrence across the 8 rows
        float wt = exp2f((float)(TT - 1 - t0) * LOG2_09);

        float acc     = 0.0f;
        float pen_sum = 0.0f;

        // rotating prefetch: PF rows (4 KB/warp) in flight
        float4 Abuf[PF], Cbuf[PF];
        #pragma unroll
        for (int k = 0; k < PF; k++) {
            const float4* p = xbase + (size_t)k * (HH / 4);
            Abuf[k] = __ldcs(p + lane);
            Cbuf[k] = __ldcs(p + 32 + lane);
        }

        #pragma unroll
        for (int i = 0; i < ROWS_PER_WARP; i++) {
            const int s = i & (PF - 1);
            float4 a  = Abuf[s];
            float4 c2 = Cbuf[s];
            if (i + PF < ROWS_PER_WARP) {
                const float4* p = xbase + (size_t)(i + PF) * (HH / 4);
                Abuf[s] = __ldcs(p + lane);
                Cbuf[s] = __ldcs(p + 32 + lane);
            }

            // c = we * w_ema[t] + wm/T  (row t=0 lacks the alpha factor)
            float c;
            if (tile == 0 && wid == 0 && i == 0) c = fmaf(we, wt, wm_over_T);
            else                                 c = fmaf(cs, wt, wm_over_T);
            wt *= INV_09;

            float p0 = a.x * wa.x;
            float p1 = a.y * wa.y;
            p0 = fmaf(a.z,  wa.z, p0);
            p1 = fmaf(a.w,  wa.w, p1);
            p0 = fmaf(c2.x, wb.x, p0);
            p1 = fmaf(c2.y, wb.y, p1);
            p0 = fmaf(c2.z, wb.z, p0);
            p1 = fmaf(c2.w, wb.w, p1);

            acc = fmaf(c, p0 + p1, acc);
            if ((penbits >> i) & 1u) pen_sum += c;
        }

        // one butterfly per warp (fixed order -> deterministic)
        #pragma unroll
        for (int off = 16; off > 0; off >>= 1)
            acc += __shfl_xor_sync(0xffffffffu, acc, off);

        if (lane == 0) s_warp_acc[wid] = acc - pen_sum * penw;
        __syncthreads();

        if (tid == 0) {
            float v = 0.0f;
            #pragma unroll
            for (int w = 0; w < NWARPS; w++) v += s_warp_acc[w];  // fixed order
            g_partial[tile] = v;
        }
        // next iteration's __syncthreads() (after s_tile write) orders reuse
    }

    // ---- completion + final fold by last CTA ----
    if (tid == 0) {
        __threadfence();
        unsigned ticket = atomicAdd(&g_done, 1u);
        s_is_last = (ticket == (unsigned)(GRID - 1));
    }
    __syncthreads();

    if (s_is_last) {
        const float bv = __ldg(bias);
        // 8 warps x 4 batches each; each batch has 64 chunk partials.
        #pragma unroll
        for (int k = 0; k < BB / NWARPS; k++) {
            const int bb = wid * (BB / NWARPS) + k;
            float v = __ldcg(&g_partial[bb * CHUNKS + lane])
                    + __ldcg(&g_partial[bb * CHUNKS + 32 + lane]);
            #pragma unroll
            for (int off = 16; off > 0; off >>= 1)
                v += __shfl_xor_sync(0xffffffffu, v, off);
            if (lane == 0) out[bb] = v + bv;
        }
        if (tid == 0) { g_work = 0; g_done = 0; }  // reset for next replay
    }
}

extern "C" void kernel_launch(void* const* d_in, const int* in_sizes, int n_in,
                              void* d_out, int out_size)
{
    const float* x    = (const float*)d_in[0];
    const int*   mask = (const int*)d_in[1];
    const float* we   = (const float*)d_in[2];
    const float* wm   = (const float*)d_in[3];
    const float* W    = (const float*)d_in[4];
    const float* bias = (const float*)d_in[5];
    float* out = (float*)d_out;

    pool_persistent<<<GRID, NTHREADS>>>(x, mask, we, wm, W, bias, out);
}